// round 6
// baseline (speedup 1.0000x reference)
#include <cuda_runtime.h>
#include <cuda_fp16.h>

#define NUM_PL 50000
#define NUM_TR 100000
#define NUM_AR 10000
#define OFF_TR NUM_PL
#define OFF_AR (NUM_PL + NUM_TR)
#define NTOT   (NUM_PL + NUM_TR + NUM_AR)
#define HID    64
#define NADJ   4200000
#define SCAN_B 1024
#define NB     ((NTOT + SCAN_B - 1) / SCAN_B)   // 157

typedef unsigned long long ull;

// -------- scratch (device globals; no runtime allocation) --------
__device__ __align__(16) float  g_x  [(size_t)NTOT * HID];
__device__ __align__(16) float  g_y  [(size_t)NTOT * HID];
__device__ __align__(16) float  g_agg[(size_t)NTOT * HID];
__device__ __align__(16) __half g_h0 [(size_t)NTOT * HID];
__device__ __align__(16) __half g_h1 [(size_t)NTOT * HID];
__device__ int   g_deg [NTOT];
__device__ float g_rdeg[NTOT];
__device__ int   g_ptr [NTOT];
__device__ int   g_cur [NTOT];
__device__ __align__(16) int g_adj [NADJ];
__device__ int   g_bsum[NB];
__device__ int   g_boff[NB];

// -------- helpers --------
__device__ __forceinline__ ull dup_f32(float x) {
    ull r; asm("mov.b64 %0, {%1,%1};" : "=l"(r) : "f"(x)); return r;
}
__device__ __forceinline__ void ffma2(ull& d, ull a, ull b) {
    asm("fma.rn.f32x2 %0, %1, %2, %3;" : "=l"(d) : "l"(a), "l"(b), "l"(d));
}
__device__ __forceinline__ float2 unpack2(ull v) {
    float2 f; asm("mov.b64 {%0,%1}, %2;" : "=f"(f.x), "=f"(f.y) : "l"(v)); return f;
}
__device__ __forceinline__ float2 h2f(unsigned u) {
    return __half22float2(*(const __half2*)&u);
}
__device__ __forceinline__ __half2 u2h(unsigned u) {
    return *(const __half2*)&u;
}
__device__ __forceinline__ unsigned f2h2(float a, float b) {
    __half2 h = __floats2half2_rn(a, b);
    return *(const unsigned*)&h;
}
__device__ __forceinline__ unsigned f2tf(float f) {
    unsigned r; asm("cvt.rna.tf32.f32 %0, %1;" : "=r"(r) : "f"(f)); return r;
}
__device__ __forceinline__ void mma_tf32(float* c, const unsigned* a, const unsigned* b) {
    asm volatile("mma.sync.aligned.m16n8k8.row.col.f32.tf32.tf32.f32 "
                 "{%0,%1,%2,%3}, {%4,%5,%6,%7}, {%8,%9}, {%0,%1,%2,%3};"
                 : "+f"(c[0]), "+f"(c[1]), "+f"(c[2]), "+f"(c[3])
                 : "r"(a[0]), "r"(a[1]), "r"(a[2]), "r"(a[3]),
                   "r"(b[0]), "r"(b[1]));
}

// -------- init playlist & artist rows --------
__global__ void init_emb_kernel(const float* __restrict__ pl_emb,
                                const float* __restrict__ ar_emb,
                                const float* __restrict__ type_emb) {
    int t = blockIdx.x * blockDim.x + threadIdx.x;
    int total = (NUM_PL + NUM_AR) * (HID / 4);
    if (t >= total) return;
    int node = t >> 4;
    int c    = (t & 15) * 4;
    const float* src; const float* ty; size_t row;
    if (node < NUM_PL) {
        src = pl_emb + (size_t)node * HID;
        row = (size_t)node * HID;
        ty  = type_emb;
    } else {
        int a = node - NUM_PL;
        src = ar_emb + (size_t)a * HID;
        row = (size_t)(OFF_AR + a) * HID;
        ty  = type_emb + 2 * HID;
    }
    float4 v  = *(const float4*)(src + c);
    float4 tv = *(const float4*)(ty  + c);
    v.x += tv.x; v.y += tv.y; v.z += tv.z; v.w += tv.w;
    *(float4*)(g_x + row + c) = v;
    uint2 h; h.x = f2h2(v.x, v.y); h.y = f2h2(v.z, v.w);
    *(uint2*)(g_h0 + row + c) = h;
}

__global__ void zero_deg_kernel() {
    int i = blockIdx.x * blockDim.x + threadIdx.x;
    if (i < NTOT) g_deg[i] = 0;
}

__global__ void deg_kernel(const int* __restrict__ s1, const int* __restrict__ d1, int n1,
                           const int* __restrict__ s2, const int* __restrict__ d2, int n2) {
    int e = blockIdx.x * blockDim.x + threadIdx.x;
    int a, b;
    if (e < n1)           { a = __ldg(s1 + e);               b = __ldg(d1 + e) + OFF_TR; }
    else if (e < n1 + n2) { a = __ldg(s2 + e - n1) + OFF_TR; b = __ldg(d2 + e - n1) + OFF_AR; }
    else return;
    atomicAdd(&g_deg[a], 1);
    atomicAdd(&g_deg[b], 1);
}

// -------- 3-pass scan --------
__device__ __forceinline__ int block_incl_scan(int v, int* warpsums) {
    int lane = threadIdx.x & 31, wid = threadIdx.x >> 5;
    int x = v;
#pragma unroll
    for (int o = 1; o < 32; o <<= 1) {
        int y = __shfl_up_sync(0xffffffffu, x, o);
        if (lane >= o) x += y;
    }
    if (lane == 31) warpsums[wid] = x;
    __syncthreads();
    if (threadIdx.x < 32) {
        int w = warpsums[threadIdx.x];
#pragma unroll
        for (int o = 1; o < 32; o <<= 1) {
            int y = __shfl_up_sync(0xffffffffu, w, o);
            if (threadIdx.x >= o) w += y;
        }
        warpsums[threadIdx.x] = w;
    }
    __syncthreads();
    if (wid > 0) x += warpsums[wid - 1];
    return x;
}

__global__ void scan_pass1() {
    __shared__ int warpsums[32];
    int i = blockIdx.x * SCAN_B + threadIdx.x;
    int v = (i < NTOT) ? g_deg[i] : 0;
    int x = block_incl_scan(v, warpsums);
    if (threadIdx.x == SCAN_B - 1) g_bsum[blockIdx.x] = x;
}

__global__ void scan_pass2() {
    __shared__ int warpsums[32];
    int i = threadIdx.x;
    int v = (i < NB) ? g_bsum[i] : 0;
    int x = block_incl_scan(v, warpsums);
    if (i < NB) g_boff[i] = x - v;
}

__global__ void scan_pass3() {
    __shared__ int warpsums[32];
    int i = blockIdx.x * SCAN_B + threadIdx.x;
    int v = (i < NTOT) ? g_deg[i] : 0;
    int x = block_incl_scan(v, warpsums);
    if (i < NTOT) {
        int excl = x - v + g_boff[blockIdx.x];
        g_ptr[i] = excl;
        g_cur[i] = excl;
        g_rdeg[i] = 1.0f / (float)(v > 0 ? v : 1);
    }
}

__global__ void fill_kernel(const int* __restrict__ s1, const int* __restrict__ d1, int n1,
                            const int* __restrict__ s2, const int* __restrict__ d2, int n2) {
    int e = blockIdx.x * blockDim.x + threadIdx.x;
    int a, b;
    if (e < n1)           { a = __ldg(s1 + e);               b = __ldg(d1 + e) + OFF_TR; }
    else if (e < n1 + n2) { a = __ldg(s2 + e - n1) + OFF_TR; b = __ldg(d2 + e - n1) + OFF_AR; }
    else return;
    int pa = atomicAdd(&g_cur[a], 1);
    g_adj[pa] = b;
    int pb = atomicAdd(&g_cur[b], 1);
    g_adj[pb] = a;
}

// -------- gather aggregation: 8 lanes/node, fp16 reads, fp32 accumulate --------
__global__ void gather_kernel(int layer) {
    const __half* __restrict__ H = layer ? g_h1 : g_h0;
    int t = blockIdx.x * blockDim.x + threadIdx.x;
    int node = t >> 3;
    if (node >= NTOT) return;
    int c = (t & 7) * 8;
    int beg = g_ptr[node];
    int d   = g_deg[node];
    float acc[8];
#pragma unroll
    for (int j = 0; j < 8; j++) acc[j] = 0.f;

    int i = 0;
    int mis = beg & 3;
    int peel = mis ? (4 - mis) : 0;
    if (peel > d) peel = d;
    for (; i < peel; i++) {
        int s = __ldg(g_adj + beg + i);
        uint4 v = *(const uint4*)(H + (size_t)s * HID + c);
#pragma unroll
        for (int q = 0; q < 4; q++) {
            float2 f = h2f((&v.x)[q]);
            acc[q * 2 + 0] += f.x; acc[q * 2 + 1] += f.y;
        }
    }
    for (; i + 4 <= d; i += 4) {
        int4 s = *(const int4*)(g_adj + beg + i);
        uint4 v0 = *(const uint4*)(H + (size_t)s.x * HID + c);
        uint4 v1 = *(const uint4*)(H + (size_t)s.y * HID + c);
        uint4 v2 = *(const uint4*)(H + (size_t)s.z * HID + c);
        uint4 v3 = *(const uint4*)(H + (size_t)s.w * HID + c);
#pragma unroll
        for (int q = 0; q < 4; q++) {
            __half2 sh = __hadd2(__hadd2(u2h((&v0.x)[q]), u2h((&v1.x)[q])),
                                 __hadd2(u2h((&v2.x)[q]), u2h((&v3.x)[q])));
            float2 f = __half22float2(sh);
            acc[q * 2 + 0] += f.x; acc[q * 2 + 1] += f.y;
        }
    }
    for (; i < d; i++) {
        int s = __ldg(g_adj + beg + i);
        uint4 v = *(const uint4*)(H + (size_t)s * HID + c);
#pragma unroll
        for (int q = 0; q < 4; q++) {
            float2 f = h2f((&v.x)[q]);
            acc[q * 2 + 0] += f.x; acc[q * 2 + 1] += f.y;
        }
    }

    float rd = g_rdeg[node];
    float4 o0, o1;
    o0.x = acc[0] * rd; o0.y = acc[1] * rd; o0.z = acc[2] * rd; o0.w = acc[3] * rd;
    o1.x = acc[4] * rd; o1.y = acc[5] * rd; o1.z = acc[6] * rd; o1.w = acc[7] * rd;
    float* dst = g_agg + (size_t)node * HID + c;
    *(float4*)dst       = o0;
    *(float4*)(dst + 4) = o1;
}

// -------- track GEMM (exact f32x2 path): g_x[tr] = track_x @ W^T + b + type_emb[1] --------
__global__ void __launch_bounds__(128) track_gemm_kernel(
        const float* __restrict__ A, const float* __restrict__ W,
        const float* __restrict__ bias, const float* __restrict__ bias2) {
    __shared__ float Ws[64][68];
    __shared__ float rows[128][36];
    const int tid = threadIdx.x;
    const int tx  = tid & 15;
    const int ty  = tid >> 4;
    const int nodeBase = blockIdx.x * 32;

    for (int it = 0; it < 32; it++)
        rows[tid][it] = A[(size_t)(nodeBase + it) * 128 + tid];

    ull a01[4], a23[4];
#pragma unroll
    for (int i = 0; i < 4; i++) { a01[i] = 0ull; a23[i] = 0ull; }

    for (int h = 0; h < 2; h++) {
        __syncthreads();
        for (int idx = tid; idx < 64 * 64; idx += 128) {
            int o = idx >> 6, k = idx & 63;
            Ws[k][o] = W[(size_t)o * 128 + h * 64 + k];
        }
        __syncthreads();
#pragma unroll 8
        for (int k = 0; k < 64; k++) {
            ulonglong2 rp = *(const ulonglong2*)&rows[(h << 6) + k][ty * 4];
            float4 w = *(const float4*)&Ws[k][tx * 4];
            ull w0 = dup_f32(w.x), w1 = dup_f32(w.y);
            ull w2 = dup_f32(w.z), w3 = dup_f32(w.w);
            ffma2(a01[0], rp.x, w0); ffma2(a23[0], rp.y, w0);
            ffma2(a01[1], rp.x, w1); ffma2(a23[1], rp.y, w1);
            ffma2(a01[2], rp.x, w2); ffma2(a23[2], rp.y, w2);
            ffma2(a01[3], rp.x, w3); ffma2(a23[3], rp.y, w3);
        }
    }

    const int o = tx * 4;
    float b0 = bias[o] + bias2[o],         b1 = bias[o + 1] + bias2[o + 1];
    float b2 = bias[o + 2] + bias2[o + 2], b3 = bias[o + 3] + bias2[o + 3];
    float res[4][4];
#pragma unroll
    for (int i = 0; i < 4; i++) {
        float2 p = unpack2(a01[i]);
        float2 q = unpack2(a23[i]);
        res[0][i] = p.x; res[1][i] = p.y; res[2][i] = q.x; res[3][i] = q.y;
    }
#pragma unroll
    for (int j = 0; j < 4; j++) {
        size_t row = (size_t)(nodeBase + ty * 4 + j + OFF_TR) * HID;
        float4 r;
        r.x = res[j][0] + b0; r.y = res[j][1] + b1;
        r.z = res[j][2] + b2; r.w = res[j][3] + b3;
        *(float4*)(g_x + row + o) = r;
        uint2 hh; hh.x = f2h2(r.x, r.y); hh.y = f2h2(r.z, r.w);
        *(uint2*)(g_h0 + row + o) = hh;
    }
}

// -------- conv layer GEMM via tf32 mma.sync --------
// out[n,o] = relu( [agg|x] @ [Wl|Wr]^T + bias ), 32 nodes/block, 4 warps.
// warp -> (mHalf = warp&1: 16-node stripe, nHalf = warp>>1: 32-col stripe)
#define LDA_S 132
__global__ void __launch_bounds__(128) conv_mma_kernel(
        int layer,
        const float* __restrict__ Wl, const float* __restrict__ Wr,
        const float* __restrict__ bias,
        float* __restrict__ outExt) {
    extern __shared__ unsigned sm[];
    unsigned* As = sm;                 // [32][LDA_S] tf32 bits
    unsigned* Bs = sm + 32 * LDA_S;    // [64][LDA_S] tf32 bits
    const float* __restrict__ X = layer ? g_y : g_x;

    const int tid  = threadIdx.x;
    const int lane = tid & 31;
    const int warp = tid >> 5;
    const int nodeBase = blockIdx.x * 32;

    // stage A rows = [agg | x], pre-converted to tf32
    for (int idx = tid; idx < 32 * 128; idx += 128) {
        int n = idx >> 7, k = idx & 127;
        float v = (k < HID) ? g_agg[(size_t)(nodeBase + n) * HID + k]
                            : X[(size_t)(nodeBase + n) * HID + (k - HID)];
        As[n * LDA_S + k] = f2tf(v);
    }
    // stage W cat = [Wl | Wr], tf32
    for (int idx = tid; idx < 64 * 128; idx += 128) {
        int o = idx >> 7, k = idx & 127;
        float v = (k < HID) ? Wl[o * HID + k] : Wr[o * HID + (k - HID)];
        Bs[o * LDA_S + k] = f2tf(v);
    }
    __syncthreads();

    const int mHalf = warp & 1;
    const int nHalf = warp >> 1;
    const int ar = mHalf * 16 + (lane >> 2);   // A row (lower of pair)
    const int ac = lane & 3;                   // A col within k-step
    const int bn = (lane >> 2);                // B n within 8-tile
    const int bk = lane & 3;                   // B k within k-step

    float c[4][4];
#pragma unroll
    for (int j = 0; j < 4; j++)
#pragma unroll
        for (int i = 0; i < 4; i++) c[j][i] = 0.f;

#pragma unroll 4
    for (int k0 = 0; k0 < 128; k0 += 8) {
        unsigned a[4];
        a[0] = As[ar * LDA_S + k0 + ac];
        a[1] = As[(ar + 8) * LDA_S + k0 + ac];
        a[2] = As[ar * LDA_S + k0 + ac + 4];
        a[3] = As[(ar + 8) * LDA_S + k0 + ac + 4];
#pragma unroll
        for (int j = 0; j < 4; j++) {
            const unsigned* brow = Bs + (nHalf * 32 + j * 8 + bn) * LDA_S + k0;
            unsigned b[2];
            b[0] = brow[bk];
            b[1] = brow[bk + 4];
            mma_tf32(c[j], a, b);
        }
    }

    // epilogue: bias + relu + store (+ fp16 shadow for layer 0)
    const int row0 = nodeBase + mHalf * 16 + (lane >> 2);
#pragma unroll
    for (int j = 0; j < 4; j++) {
        int col = nHalf * 32 + j * 8 + (lane & 3) * 2;
        float bc0 = bias[col], bc1 = bias[col + 1];
        float2 r0, r1;
        r0.x = fmaxf(c[j][0] + bc0, 0.f);
        r0.y = fmaxf(c[j][1] + bc1, 0.f);
        r1.x = fmaxf(c[j][2] + bc0, 0.f);
        r1.y = fmaxf(c[j][3] + bc1, 0.f);
        if (layer == 0) {
            *(float2*)(g_y + (size_t)row0 * HID + col)       = r0;
            *(float2*)(g_y + (size_t)(row0 + 8) * HID + col) = r1;
            *(unsigned*)(g_h1 + (size_t)row0 * HID + col)       = f2h2(r0.x, r0.y);
            *(unsigned*)(g_h1 + (size_t)(row0 + 8) * HID + col) = f2h2(r1.x, r1.y);
        } else {
            *(float2*)(outExt + (size_t)row0 * HID + col)       = r0;
            *(float2*)(outExt + (size_t)(row0 + 8) * HID + col) = r1;
        }
    }
}

extern "C" void kernel_launch(void* const* d_in, const int* in_sizes, int n_in,
                              void* d_out, int out_size) {
    const float* track_x   = (const float*)d_in[0];
    const int*   pl_tr_src = (const int*)d_in[1];
    const int*   pl_tr_dst = (const int*)d_in[2];
    const int*   tr_ar_src = (const int*)d_in[3];
    const int*   tr_ar_dst = (const int*)d_in[4];
    const float* pl_emb    = (const float*)d_in[5];
    const float* ar_emb    = (const float*)d_in[6];
    const float* track_W   = (const float*)d_in[7];
    const float* track_b   = (const float*)d_in[8];
    const float* type_emb  = (const float*)d_in[9];
    const float* conv_Wl   = (const float*)d_in[10];
    const float* conv_bl   = (const float*)d_in[11];
    const float* conv_Wr   = (const float*)d_in[12];
    float* out = (float*)d_out;

    const int E1 = in_sizes[1];
    const int E2 = in_sizes[3];
    const int ET = E1 + E2;

    const int convSmem = (32 + 64) * LDA_S * 4;   // 50688 B
    cudaFuncSetAttribute(conv_mma_kernel,
                         cudaFuncAttributeMaxDynamicSharedMemorySize, convSmem);

    // ---- CSR build first (slot 6 = fill_kernel for ncu -s 5 -c 1) ----
    zero_deg_kernel<<<(NTOT + 255) / 256, 256>>>();                                  // 1
    deg_kernel<<<(ET + 255) / 256, 256>>>(pl_tr_src, pl_tr_dst, E1,
                                          tr_ar_src, tr_ar_dst, E2);                 // 2
    scan_pass1<<<NB, SCAN_B>>>();                                                    // 3
    scan_pass2<<<1, 256>>>();                                                        // 4
    scan_pass3<<<NB, SCAN_B>>>();                                                    // 5
    fill_kernel<<<(ET + 255) / 256, 256>>>(pl_tr_src, pl_tr_dst, E1,
                                           tr_ar_src, tr_ar_dst, E2);                // 6

    // ---- node features ----
    {
        int total = (NUM_PL + NUM_AR) * (HID / 4);
        init_emb_kernel<<<(total + 255) / 256, 256>>>(pl_emb, ar_emb, type_emb);     // 7
    }
    track_gemm_kernel<<<NUM_TR / 32, 128>>>(track_x, track_W, track_b,
                                            type_emb + HID);                         // 8

    // ---- layer 0 ----
    gather_kernel<<<(NTOT * 8 + 255) / 256, 256>>>(0);                               // 9
    conv_mma_kernel<<<NTOT / 32, 128, convSmem>>>(0, conv_Wl, conv_Wr,
                                                  conv_bl, nullptr);                 // 10

    // ---- layer 1 ----
    gather_kernel<<<(NTOT * 8 + 255) / 256, 256>>>(1);                               // 11
    conv_mma_kernel<<<NTOT / 32, 128, convSmem>>>(1, conv_Wl + 64 * 64,
                                                  conv_Wr + 64 * 64,
                                                  conv_bl + 64, out);                // 12
}